// round 2
// baseline (speedup 1.0000x reference)
#include <cuda_runtime.h>
#include <math.h>

#define N_STATES 2048
#define NMASK    2047
#define V_TOK    10000
#define B_       4
#define T_       16
#define L_       16

#define FTPB 512          // forward kernel threads
#define SPT  (N_STATES / FTPB)   // 4 states per thread

// scratch: emis[b][t][n] = sum_l E_ls[n, tok[b,t,l]]
__device__ float g_emis[B_ * T_ * N_STATES];

// ---------------------------------------------------------------------------
// Kernel 1: single-pass online logsumexp per state row + token gathers.
// ---------------------------------------------------------------------------
__global__ void __launch_bounds__(256) emis_kernel(const float* __restrict__ Ew,
                                                   const int* __restrict__ stories)
{
    const int n   = blockIdx.x;
    const int tid = threadIdx.x;
    const float* __restrict__ row  = Ew + (size_t)n * V_TOK;
    const float4* __restrict__ row4 = (const float4*)row;   // n*40000 bytes, 16B aligned

    __shared__ int   s_tok[B_ * T_ * L_];
    __shared__ float s_m[8], s_s[8];
    __shared__ float s_lse;

    for (int i = tid; i < B_ * T_ * L_; i += 256) s_tok[i] = stories[i];

    // ---- online (m, s) over this thread's strided chunk ----
    float m = -INFINITY, s = 0.f;
    for (int i = tid; i < V_TOK / 4; i += 256) {
        float4 v = row4[i];
        float m4 = fmaxf(fmaxf(v.x, v.y), fmaxf(v.z, v.w));
        float mn = fmaxf(m, m4);
        s = s * __expf(m - mn)
          + __expf(v.x - mn) + __expf(v.y - mn)
          + __expf(v.z - mn) + __expf(v.w - mn);
        m = mn;
    }

    // ---- warp combine of (m, s) ----
    #pragma unroll
    for (int o = 16; o > 0; o >>= 1) {
        float om = __shfl_xor_sync(0xFFFFFFFFu, m, o);
        float os = __shfl_xor_sync(0xFFFFFFFFu, s, o);
        float mn = fmaxf(m, om);
        s = s * __expf(m - mn) + os * __expf(om - mn);
        m = mn;
    }
    if ((tid & 31) == 0) { s_m[tid >> 5] = m; s_s[tid >> 5] = s; }
    __syncthreads();
    if (tid == 0) {
        float M = s_m[0], S = s_s[0];
        #pragma unroll
        for (int j = 1; j < 8; j++) {
            float mn = fmaxf(M, s_m[j]);
            S = S * __expf(M - mn) + s_s[j] * __expf(s_m[j] - mn);
            M = mn;
        }
        s_lse = M + __logf(S);
    }
    __syncthreads();
    const float lse = s_lse;

    // ---- gather: 64 (b,t) pairs x 16 tokens (row hot in L2) ----
    if (tid < B_ * T_) {
        const int* tk = s_tok + tid * L_;
        float g = 0.f;
        #pragma unroll
        for (int l = 0; l < L_; l++) g += __ldg(row + tk[l]);
        g_emis[tid * N_STATES + n] = g - (float)L_ * lse;
    }
}

// ---------------------------------------------------------------------------
// Kernel 2: forward recurrence in shared-normalizer probability space.
//   Texp = softmax(trans_w) (computed once); per step:
//     p[h]  = exp(alpha[h] - m_prev)                (1 exp / state)
//     a'[h] = emis + m_prev + log(sum_i Texp_i[h] * p[n_i])   (1 log / state)
//   m_prev = block max of previous alpha, reduced during the write phase.
// Transition band: delta=2048 aliases delta=0; scatter-set order => slot 6
// wins the diagonal, slot 0 is dead.
// ---------------------------------------------------------------------------
__global__ void __launch_bounds__(FTPB) forward_kernel(
    const float* __restrict__ trans_w,
    const float* __restrict__ prior_w,
    float* __restrict__ out)
{
    extern __shared__ float sm[];
    float* Texp = sm;                       // [6][N] transition probabilities
    float* abuf = sm + 6 * N_STATES;        // [2][N] alpha double buffer
    float* pbuf = sm + 8 * N_STATES;        // [N]    exp(alpha - m)
    __shared__ float s_wm[FTPB / 32];       // per-warp alpha maxes
    __shared__ float s_red[FTPB / 32];
    __shared__ float s_plse;

    const int b    = blockIdx.x;
    const int tid  = threadIdx.x;
    const int wid  = tid >> 5;
    const int lane = tid & 31;

    // ---- transition softmax over 7 slots (keep 6,1,2,3,4,5) ----
    for (int h = tid; h < N_STATES; h += FTPB) {
        float w[7];
        #pragma unroll
        for (int j = 0; j < 7; j++) w[j] = trans_w[h * 7 + j];
        float m = w[0];
        #pragma unroll
        for (int j = 1; j < 7; j++) m = fmaxf(m, w[j]);
        float e[7], s = 0.f;
        #pragma unroll
        for (int j = 0; j < 7; j++) { e[j] = __expf(w[j] - m); s += e[j]; }
        const float inv = 1.0f / s;
        Texp[0 * N_STATES + h] = e[6] * inv;   // diagonal (slot 6 wins)
        Texp[1 * N_STATES + h] = e[1] * inv;   // from (h-1)
        Texp[2 * N_STATES + h] = e[2] * inv;   // from (h+1)
        Texp[3 * N_STATES + h] = e[3] * inv;   // from (h-32)
        Texp[4 * N_STATES + h] = e[4] * inv;   // from (h+32)
        Texp[5 * N_STATES + h] = e[5] * inv;   // from (h-1024)
    }

    // ---- prior logsumexp ----
    float pm = -INFINITY;
    for (int h = tid; h < N_STATES; h += FTPB) pm = fmaxf(pm, prior_w[h]);
    #pragma unroll
    for (int o = 16; o > 0; o >>= 1) pm = fmaxf(pm, __shfl_xor_sync(0xFFFFFFFFu, pm, o));
    if (lane == 0) s_red[wid] = pm;
    __syncthreads();
    float PM = -INFINITY;
    #pragma unroll
    for (int j = 0; j < FTPB / 32; j++) PM = fmaxf(PM, s_red[j]);
    __syncthreads();

    float ps = 0.f;
    for (int h = tid; h < N_STATES; h += FTPB) ps += __expf(prior_w[h] - PM);
    #pragma unroll
    for (int o = 16; o > 0; o >>= 1) ps += __shfl_xor_sync(0xFFFFFFFFu, ps, o);
    if (lane == 0) s_red[wid] = ps;
    __syncthreads();
    if (tid == 0) {
        float ss = 0.f;
        #pragma unroll
        for (int j = 0; j < FTPB / 32; j++) ss += s_red[j];
        s_plse = PM + __logf(ss);
    }
    __syncthreads();
    const float plse = s_plse;

    // ---- alpha0 (track max for step 1 normalizer) ----
    const float* __restrict__ emisb = g_emis + (size_t)b * T_ * N_STATES;
    float lmax = -INFINITY;
    #pragma unroll
    for (int k = 0; k < SPT; k++) {
        const int h = tid + k * FTPB;
        const float a = emisb[h] + prior_w[h] - plse;
        abuf[h] = a;
        out[b * N_STATES + h] = a;
        lmax = fmaxf(lmax, a);
    }
    #pragma unroll
    for (int o = 16; o > 0; o >>= 1) lmax = fmaxf(lmax, __shfl_xor_sync(0xFFFFFFFFu, lmax, o));
    if (lane == 0) s_wm[wid] = lmax;
    __syncthreads();

    // ---- recurrence ----
    int cur = 0;
    for (int t = 1; t < T_; t++) {
        const float* __restrict__ ao = abuf + cur * N_STATES;
        float* __restrict__       an = abuf + (cur ^ 1) * N_STATES;

        // block max of previous alpha (16 broadcast LDS, no extra sync)
        float m = -INFINITY;
        #pragma unroll
        for (int j = 0; j < FTPB / 32; j++) m = fmaxf(m, s_wm[j]);

        // phase A: shared exp table
        #pragma unroll
        for (int k = 0; k < SPT; k++) {
            const int h = tid + k * FTPB;
            pbuf[h] = __expf(ao[h] - m);
        }
        __syncthreads();

        // phase B: 6-tap weighted sum + log
        float nmax = -INFINITY;
        #pragma unroll
        for (int k = 0; k < SPT; k++) {
            const int h = tid + k * FTPB;
            float s;
            s =        Texp[0 * N_STATES + h] * pbuf[h];
            s = fmaf(Texp[1 * N_STATES + h], pbuf[(h - 1)    & NMASK], s);
            s = fmaf(Texp[2 * N_STATES + h], pbuf[(h + 1)    & NMASK], s);
            s = fmaf(Texp[3 * N_STATES + h], pbuf[(h - 32)   & NMASK], s);
            s = fmaf(Texp[4 * N_STATES + h], pbuf[(h + 32)   & NMASK], s);
            s = fmaf(Texp[5 * N_STATES + h], pbuf[(h - 1024) & NMASK], s);
            s = fmaxf(s, 1e-37f);  // underflow guard (norm-negligible)
            const float a = emisb[t * N_STATES + h] + m + __logf(s);
            an[h] = a;
            out[(size_t)t * B_ * N_STATES + b * N_STATES + h] = a;
            nmax = fmaxf(nmax, a);
        }
        #pragma unroll
        for (int o = 16; o > 0; o >>= 1) nmax = fmaxf(nmax, __shfl_xor_sync(0xFFFFFFFFu, nmax, o));
        if (lane == 0) s_wm[wid] = nmax;
        cur ^= 1;
        __syncthreads();
    }
}

// ---------------------------------------------------------------------------
extern "C" void kernel_launch(void* const* d_in, const int* in_sizes, int n_in,
                              void* d_out, int out_size)
{
    const int*   stories = nullptr;
    const float* trans_w = nullptr;
    const float* emis_w  = nullptr;
    const float* prior_w = nullptr;
    for (int i = 0; i < n_in; i++) {
        switch (in_sizes[i]) {
            case B_ * T_ * L_:     stories = (const int*)d_in[i];   break;
            case N_STATES * 7:     trans_w = (const float*)d_in[i]; break;
            case N_STATES * V_TOK: emis_w  = (const float*)d_in[i]; break;
            case N_STATES:         prior_w = (const float*)d_in[i]; break;
            default: break; // story_length scalar unused (compile-time T_)
        }
    }
    float* out = (float*)d_out;

    emis_kernel<<<N_STATES, 256>>>(emis_w, stories);

    const int smem = 9 * N_STATES * (int)sizeof(float); // 72 KB
    static bool attr_set = false;
    if (!attr_set) {
        cudaFuncSetAttribute(forward_kernel,
                             cudaFuncAttributeMaxDynamicSharedMemorySize, smem);
        attr_set = true;
    }
    forward_kernel<<<B_, FTPB, smem>>>(trans_w, prior_w, out);
}

// round 3
// speedup vs baseline: 1.4019x; 1.4019x over previous
#include <cuda_runtime.h>
#include <math.h>

#define N_STATES 2048
#define NMASK    2047
#define V_TOK    10000
#define B_       4
#define T_       16
#define L_       16

#define FTPB 1024
#define SPT  2            // states per thread

// scratch: emis[b][t][n] = sum_l E_ls[n, tok[b,t,l]]
__device__ float g_emis[B_ * T_ * N_STATES];

// ---------------------------------------------------------------------------
// Kernel 1: single-pass online logsumexp per state row + token gathers.
// (emission matrix is L2-resident across replays: ~2.6us)
// ---------------------------------------------------------------------------
__global__ void __launch_bounds__(256) emis_kernel(const float* __restrict__ Ew,
                                                   const int* __restrict__ stories)
{
    const int n   = blockIdx.x;
    const int tid = threadIdx.x;
    const float* __restrict__ row  = Ew + (size_t)n * V_TOK;
    const float4* __restrict__ row4 = (const float4*)row;   // n*40000B, 16B aligned

    __shared__ int   s_tok[B_ * T_ * L_];
    __shared__ float s_m[8], s_s[8];
    __shared__ float s_lse;

    for (int i = tid; i < B_ * T_ * L_; i += 256) s_tok[i] = stories[i];

    float m = -INFINITY, s = 0.f;
    for (int i = tid; i < V_TOK / 4; i += 256) {
        float4 v = row4[i];
        float m4 = fmaxf(fmaxf(v.x, v.y), fmaxf(v.z, v.w));
        float mn = fmaxf(m, m4);
        s = s * __expf(m - mn)
          + __expf(v.x - mn) + __expf(v.y - mn)
          + __expf(v.z - mn) + __expf(v.w - mn);
        m = mn;
    }
    #pragma unroll
    for (int o = 16; o > 0; o >>= 1) {
        float om = __shfl_xor_sync(0xFFFFFFFFu, m, o);
        float os = __shfl_xor_sync(0xFFFFFFFFu, s, o);
        float mn = fmaxf(m, om);
        s = s * __expf(m - mn) + os * __expf(om - mn);
        m = mn;
    }
    if ((tid & 31) == 0) { s_m[tid >> 5] = m; s_s[tid >> 5] = s; }
    __syncthreads();
    if (tid == 0) {
        float M = s_m[0], S = s_s[0];
        #pragma unroll
        for (int j = 1; j < 8; j++) {
            float mn = fmaxf(M, s_m[j]);
            S = S * __expf(M - mn) + s_s[j] * __expf(s_m[j] - mn);
            M = mn;
        }
        s_lse = M + __logf(S);
    }
    __syncthreads();
    const float lse = s_lse;

    if (tid < B_ * T_) {
        const int* tk = s_tok + tid * L_;
        float g = 0.f;
        #pragma unroll
        for (int l = 0; l < L_; l++) g += __ldg(row + tk[l]);
        g_emis[tid * N_STATES + n] = g - (float)L_ * lse;
    }
}

// ---------------------------------------------------------------------------
// Kernel 2: forward recurrence, shared-normalizer probability space.
// alpha + Texp in registers; only p = exp(alpha - m) goes through smem.
// Transition band: delta=2048 aliases delta=0 (mod N); scatter-set order
// means slot 6 wins the diagonal, slot 0 is dead.
// ---------------------------------------------------------------------------
__global__ void __launch_bounds__(FTPB) forward_kernel(
    const float* __restrict__ trans_w,
    const float* __restrict__ prior_w,
    float* __restrict__ out)
{
    __shared__ float pbuf[N_STATES];
    __shared__ float s_wm[32];     // per-warp partial maxes (32 warps exactly)
    __shared__ float s_plse;

    const int b    = blockIdx.x;
    const int tid  = threadIdx.x;
    const int wid  = tid >> 5;
    const int lane = tid & 31;

    // ---- per-thread transition softmax for own states (stays in regs) ----
    float Tt[SPT][6];
    int   h_[SPT];
    int   ix[SPT][5];
    #pragma unroll
    for (int k = 0; k < SPT; k++) {
        const int h = tid + k * FTPB;
        h_[k] = h;
        ix[k][0] = (h - 1)    & NMASK;
        ix[k][1] = (h + 1)    & NMASK;
        ix[k][2] = (h - 32)   & NMASK;
        ix[k][3] = (h + 32)   & NMASK;
        ix[k][4] = (h - 1024) & NMASK;
        float w[7];
        #pragma unroll
        for (int j = 0; j < 7; j++) w[j] = __ldg(trans_w + h * 7 + j);
        float m = w[0];
        #pragma unroll
        for (int j = 1; j < 7; j++) m = fmaxf(m, w[j]);
        float e[7], s = 0.f;
        #pragma unroll
        for (int j = 0; j < 7; j++) { e[j] = __expf(w[j] - m); s += e[j]; }
        const float inv = 1.0f / s;
        Tt[k][0] = e[6] * inv;   // diagonal (slot 6 wins over slot 0)
        Tt[k][1] = e[1] * inv;   // from (h-1)
        Tt[k][2] = e[2] * inv;   // from (h+1)
        Tt[k][3] = e[3] * inv;   // from (h-32)
        Tt[k][4] = e[4] * inv;   // from (h+32)
        Tt[k][5] = e[5] * inv;   // from (h-1024)
    }

    // ---- prior logsumexp ----
    float pw[SPT];
    #pragma unroll
    for (int k = 0; k < SPT; k++) pw[k] = __ldg(prior_w + h_[k]);

    float pm = fmaxf(pw[0], pw[1]);
    #pragma unroll
    for (int o = 16; o > 0; o >>= 1) pm = fmaxf(pm, __shfl_xor_sync(0xFFFFFFFFu, pm, o));
    if (lane == 0) s_wm[wid] = pm;
    __syncthreads();
    float PM = s_wm[lane];
    #pragma unroll
    for (int o = 16; o > 0; o >>= 1) PM = fmaxf(PM, __shfl_xor_sync(0xFFFFFFFFu, PM, o));
    __syncthreads();

    float ps = __expf(pw[0] - PM) + __expf(pw[1] - PM);
    #pragma unroll
    for (int o = 16; o > 0; o >>= 1) ps += __shfl_xor_sync(0xFFFFFFFFu, ps, o);
    if (lane == 0) s_wm[wid] = ps;
    __syncthreads();
    if (tid == 0) {
        float ss = 0.f;
        #pragma unroll
        for (int j = 0; j < 32; j++) ss += s_wm[j];
        s_plse = PM + __logf(ss);
    }
    __syncthreads();
    const float plse = s_plse;

    // ---- alpha0 (in registers) ----
    const float* __restrict__ ep   = g_emis + (size_t)b * T_ * N_STATES;
    float*       __restrict__ outp = out + b * N_STATES;
    float a[SPT];
    #pragma unroll
    for (int k = 0; k < SPT; k++) {
        a[k] = __ldg(ep + h_[k]) + pw[k] - plse;
        outp[h_[k]] = a[k];
    }
    float nm = fmaxf(a[0], a[1]);
    #pragma unroll
    for (int o = 16; o > 0; o >>= 1) nm = fmaxf(nm, __shfl_xor_sync(0xFFFFFFFFu, nm, o));
    if (lane == 0) s_wm[wid] = nm;
    __syncthreads();

    // ---- recurrence: 16 steps, 2 barriers each ----
    for (int t = 1; t < T_; t++) {
        ep   += N_STATES;
        outp += B_ * N_STATES;

        // phase A: block max of prev alpha, publish p = exp(a - m)
        float m = s_wm[lane];
        #pragma unroll
        for (int o = 16; o > 0; o >>= 1) m = fmaxf(m, __shfl_xor_sync(0xFFFFFFFFu, m, o));

        float p[SPT], em[SPT];
        #pragma unroll
        for (int k = 0; k < SPT; k++) {
            p[k] = __expf(a[k] - m);
            pbuf[h_[k]] = p[k];
            em[k] = __ldg(ep + h_[k]);   // prefetch emission (L2) across barrier
        }
        __syncthreads();

        // phase B: 6-tap weighted sum + log
        #pragma unroll
        for (int k = 0; k < SPT; k++) {
            float s = Tt[k][0] * p[k];
            s = fmaf(Tt[k][1], pbuf[ix[k][0]], s);
            s = fmaf(Tt[k][2], pbuf[ix[k][1]], s);
            s = fmaf(Tt[k][3], pbuf[ix[k][2]], s);
            s = fmaf(Tt[k][4], pbuf[ix[k][3]], s);
            s = fmaf(Tt[k][5], pbuf[ix[k][4]], s);
            s = fmaxf(s, 1e-37f);        // underflow guard
            a[k] = em[k] + m + __logf(s);
            outp[h_[k]] = a[k];
        }
        float wm = fmaxf(a[0], a[1]);
        #pragma unroll
        for (int o = 16; o > 0; o >>= 1) wm = fmaxf(wm, __shfl_xor_sync(0xFFFFFFFFu, wm, o));
        if (lane == 0) s_wm[wid] = wm;
        __syncthreads();
    }
}

// ---------------------------------------------------------------------------
extern "C" void kernel_launch(void* const* d_in, const int* in_sizes, int n_in,
                              void* d_out, int out_size)
{
    const int*   stories = nullptr;
    const float* trans_w = nullptr;
    const float* emis_w  = nullptr;
    const float* prior_w = nullptr;
    for (int i = 0; i < n_in; i++) {
        switch (in_sizes[i]) {
            case B_ * T_ * L_:     stories = (const int*)d_in[i];   break;
            case N_STATES * 7:     trans_w = (const float*)d_in[i]; break;
            case N_STATES * V_TOK: emis_w  = (const float*)d_in[i]; break;
            case N_STATES:         prior_w = (const float*)d_in[i]; break;
            default: break; // story_length scalar unused (compile-time T_)
        }
    }
    float* out = (float*)d_out;

    emis_kernel<<<N_STATES, 256>>>(emis_w, stories);
    forward_kernel<<<B_, FTPB>>>(trans_w, prior_w, out);
}